// round 8
// baseline (speedup 1.0000x reference)
#include <cuda_runtime.h>
#include <cuda_fp16.h>
#include <cstdint>

// ModulatedConv2d B=8, Cin=Cout=512, K=3, H=W=64
// fp16 mma.sync m16n8k16 implicit GEMM; tap-resident stages, BM=256, 512 threads.

#define B_      8
#define CIN     512
#define COUT    512
#define HW2     4096
#define WPAD    66
#define MPLANE  4224        // 64 rows * 66
#define LIN_SCALE   0.044194173824159216f
#define CONV_SCALE  0.014731391274719739f
#define EPS_        1e-8f

// ---------------- device scratch ----------------
__device__ float  g_s[B_ * CIN];
__device__ float  g_scale[B_ * COUT];
__device__ float  g_wsq[COUT * CIN];
__device__ __half g_xt[(size_t)B_ * MPLANE * CIN];
__device__ __half g_wt[9ull * COUT * CIN];

// ---------------- helpers ----------------
__device__ __forceinline__ uint32_t smem_u32(const void* p) {
    uint32_t a;
    asm("{ .reg .u64 t; cvta.to.shared.u64 t, %1; cvt.u32.u64 %0, t; }" : "=r"(a) : "l"(p));
    return a;
}
__device__ __forceinline__ void cp16(uint32_t dst, const void* src, int srcsize) {
    asm volatile("cp.async.ca.shared.global [%0], [%1], 16, %2;"
                 :: "r"(dst), "l"(src), "r"(srcsize) : "memory");
}
#define CP_COMMIT() asm volatile("cp.async.commit_group;" ::: "memory")
#define CP_WAIT(n)  asm volatile("cp.async.wait_group %0;" :: "n"(n) : "memory")

__device__ __forceinline__ void ldsm4(uint32_t* r, uint32_t addr) {
    asm volatile("ldmatrix.sync.aligned.m8n8.x4.shared.b16 {%0,%1,%2,%3}, [%4];"
        : "=r"(r[0]), "=r"(r[1]), "=r"(r[2]), "=r"(r[3]) : "r"(addr));
}
__device__ __forceinline__ void mma_f16(float* d, const uint32_t* a, const uint32_t* b) {
    asm volatile(
        "mma.sync.aligned.m16n8k16.row.col.f32.f16.f16.f32 "
        "{%0,%1,%2,%3}, {%4,%5,%6,%7}, {%8,%9}, {%0,%1,%2,%3};"
        : "+f"(d[0]), "+f"(d[1]), "+f"(d[2]), "+f"(d[3])
        : "r"(a[0]), "r"(a[1]), "r"(a[2]), "r"(a[3]), "r"(b[0]), "r"(b[1]));
}

// ---------------- prep1: style (blocks 0..31) + wtrans (blocks 32..543), 512 thr ----
__global__ void prep1_kernel(const float* __restrict__ style,
                             const float* __restrict__ modw,
                             const float* __restrict__ modb,
                             const float* __restrict__ weight,
                             float* __restrict__ out_s5) {
    int blk = blockIdx.x, t = threadIdx.x;
    if (blk < 32) {
        __shared__ float st[512];
        int b = blk >> 2;
        st[t] = style[b * 512 + t];
        __syncthreads();
        int ci = (blk & 3) * 128 + (t >> 2);
        int part = t & 3;
        const float4* mrow = (const float4*)(modw + (size_t)ci * 512) + part * 32;
        const float4* s4 = (const float4*)st + part * 32;
        float a0 = 0.f, a1 = 0.f, a2 = 0.f, a3 = 0.f;
#pragma unroll
        for (int j = 0; j < 32; ++j) {
            float4 m = mrow[j], s = s4[j];
            a0 = fmaf(s.x, m.x, a0);
            a1 = fmaf(s.y, m.y, a1);
            a2 = fmaf(s.z, m.z, a2);
            a3 = fmaf(s.w, m.w, a3);
        }
        float acc = (a0 + a1) + (a2 + a3);
        acc += __shfl_xor_sync(0xffffffffu, acc, 1);
        acc += __shfl_xor_sync(0xffffffffu, acc, 2);
        if (part == 0) {
            float s = acc * LIN_SCALE + modb[ci];
            g_s[b * 512 + ci] = s;
            out_s5[b * 512 + ci] = s;
        }
    } else {
        int co = blk - 32, ci = t;
        const float* wp = weight + ((size_t)co * 512 + ci) * 9;
        float w[9], q = 0.f;
#pragma unroll
        for (int k = 0; k < 9; ++k) { w[k] = wp[k]; q = fmaf(w[k], w[k], q); }
        g_wsq[co * 512 + ci] = q;
#pragma unroll
        for (int k = 0; k < 9; ++k)
            g_wt[((size_t)k * COUT + co) * 512 + ci] = __float2half_rn(w[k]);
    }
}

// ---------------- prep2: demod (blocks 0..127) + modxt (blocks 128..2175), 256 thr ----
__global__ void prep2_kernel(const float* __restrict__ x) {
    int blk = blockIdx.x, t = threadIdx.x;
    if (blk < 128) {
        __shared__ float s2[512];
        int b = blk >> 4;
        float sv = g_s[b * 512 + t];
        s2[t] = sv * sv;
        sv = g_s[b * 512 + t + 256];
        s2[t + 256] = sv * sv;
        __syncthreads();
        int co = (blk & 15) * 32 + (t >> 3);
        int part = t & 7;
        const float4* wq = (const float4*)(g_wsq + (size_t)co * 512) + part * 16;
        const float4* s4 = (const float4*)s2 + part * 16;
        float a0 = 0.f, a1 = 0.f, a2 = 0.f, a3 = 0.f;
#pragma unroll
        for (int j = 0; j < 16; ++j) {
            float4 m = wq[j], s = s4[j];
            a0 = fmaf(s.x, m.x, a0);
            a1 = fmaf(s.y, m.y, a1);
            a2 = fmaf(s.z, m.z, a2);
            a3 = fmaf(s.w, m.w, a3);
        }
        float acc = (a0 + a1) + (a2 + a3);
        acc += __shfl_xor_sync(0xffffffffu, acc, 1);
        acc += __shfl_xor_sync(0xffffffffu, acc, 2);
        acc += __shfl_xor_sync(0xffffffffu, acc, 4);
        if (part == 0)
            g_scale[b * 512 + co] = CONV_SCALE * rsqrtf(CONV_SCALE * CONV_SCALE * acc + EPS_);
    } else {
        __shared__ float tt[64][65];
        int idx = blk - 128;               // 0..2047
        int cg  = idx & 3;
        int row = (idx >> 2) & 63;
        int b   = idx >> 8;
        __half* obase = g_xt + ((size_t)b * MPLANE + (size_t)row * WPAD) * CIN;
        if (t < 256) {
            int which = t >> 7, col = (t & 127) + cg * 128;
            obase[(size_t)which * 65 * CIN + col] = __float2half_rn(0.f);
        }
        for (int cc = 0; cc < 2; ++cc) {
            int cic = cg * 2 + cc;
            __syncthreads();
            for (int i = t; i < 4096; i += 256) {
                int ci = i >> 6, w = i & 63;
                float s = g_s[b * 512 + cic * 64 + ci];
                tt[ci][w] = x[((size_t)(b * 512 + cic * 64 + ci)) * HW2 + row * 64 + w] * s;
            }
            __syncthreads();
            for (int i = t; i < 4096; i += 256) {
                int w = i >> 6, ci = i & 63;
                obase[(size_t)(1 + w) * CIN + cic * 64 + ci] = __float2half_rn(tt[ci][w]);
            }
        }
    }
}

// ---------------- conv: tap-resident fp16 GEMM, BM=256 ----------------
// Stage = (kc: 32 ci, kh). A slab (258 rows, kw halo) + 3 kw weight tiles.
// 48 stages, 3-stage ring, 512 threads, 1 CTA/SM.
#define BM 256
#define BN 128
#define KSTR 40                      // smem row stride (halves)
#define AROWS 260
#define ASZH (AROWS * KSTR)          // 10400 halves
#define BSZH (3 * 128 * KSTR)        // 15360 halves
#define ABYTES (ASZH * 2)            // 20800
#define STAGEB ((ASZH + BSZH) * 2)   // 51520
#define NST 48
#define SMEM_TOTAL (3 * STAGEB)      // 154560

__global__ __launch_bounds__(512, 1)
void conv_kernel(float* __restrict__ out) {
    extern __shared__ char smch[];

    const int tid = threadIdx.x;
    const int warp = tid >> 5, lane = tid & 31;
    const int wm = warp & 3;             // 0..3 -> 64-row slice of 256
    const int wn = warp >> 2;            // 0..3 -> 32-col slice of 128
    const int gid = lane >> 2;
    const int tig = lane & 3;

    const int co0 = blockIdx.x * BN;
    const int p0 = blockIdx.y * BM;
    const int b = blockIdx.z;

    const __half* Abase = g_xt + (size_t)b * MPLANE * CIN;
    const uint32_t sb = smem_u32(smch);

    const uint32_t a_loff = (((lane & 7) + ((lane >> 3) & 1) * 8) * KSTR + (lane >> 4) * 8) * 2u;
    const uint32_t b_loff = (((lane & 7) + ((lane >> 4) & 1) * 8) * KSTR + ((lane >> 3) & 1) * 8) * 2u;

    float d[4][4][4];
#pragma unroll
    for (int i = 0; i < 4; ++i)
#pragma unroll
        for (int j = 0; j < 4; ++j)
#pragma unroll
            for (int k = 0; k < 4; ++k) d[i][j][k] = 0.f;

    auto load_stage = [&](int s, int buf) {
        const int kc = s / 3, kh = s % 3;
        const uint32_t a0 = sb + (uint32_t)buf * STAGEB;
        const uint32_t b0 = a0 + ABYTES;
        const int prbase = p0 + (kh - 1) * WPAD - 1;
        // A: 258 rows x 4 q = 1032 cp16
#pragma unroll
        for (int i = 0; i < 3; ++i) {
            int idx = tid + i * 512;
            if (idx < 1032) {
                int row = idx >> 2, q = idx & 3;
                int pr = prbase + row;
                const __half* src = Abase + (size_t)pr * CIN + kc * 32 + q * 8;
                int sz = ((unsigned)pr < (unsigned)MPLANE) ? 16 : 0;
                cp16(a0 + (uint32_t)(row * KSTR + q * 8) * 2u, src, sz);
            }
        }
        // B: 3 kw x 128 co x 4 q = 1536 cp16
#pragma unroll
        for (int i = 0; i < 3; ++i) {
            int idx = tid + i * 512;
            int kw = idx >> 9;
            int r = idx & 511;
            int co = r >> 2, q = r & 3;
            const __half* src = g_wt + ((size_t)(kh * 3 + kw) * COUT + co0 + co) * CIN
                                + kc * 32 + q * 8;
            cp16(b0 + (uint32_t)((kw * 128 + co) * KSTR + q * 8) * 2u, src, 16);
        }
        CP_COMMIT();
    };

    load_stage(0, 0);
    load_stage(1, 1);

    for (int s = 0; s < NST; ++s) {
        CP_WAIT(1);
        __syncthreads();
        if (s + 2 < NST) load_stage(s + 2, (s + 2) % 3);

        const uint32_t a0 = sb + (uint32_t)(s % 3) * STAGEB;
        const uint32_t b0 = a0 + ABYTES;
#pragma unroll
        for (int kw = 0; kw < 3; ++kw) {
#pragma unroll
            for (int ks = 0; ks < 2; ++ks) {
                const int kb = ks * 16;
                uint32_t a[4][4];
#pragma unroll
                for (int fm = 0; fm < 4; ++fm)
                    ldsm4(a[fm], a0 + (uint32_t)((wm * 64 + fm * 16 + kw) * KSTR + kb) * 2u + a_loff);
                uint32_t bf[4][2];
#pragma unroll
                for (int j = 0; j < 2; ++j) {
                    uint32_t r[4];
                    ldsm4(r, b0 + (uint32_t)((kw * 128 + wn * 32 + j * 16) * KSTR + kb) * 2u + b_loff);
                    bf[2 * j][0] = r[0]; bf[2 * j][1] = r[1];
                    bf[2 * j + 1][0] = r[2]; bf[2 * j + 1][1] = r[3];
                }
#pragma unroll
                for (int fm = 0; fm < 4; ++fm)
#pragma unroll
                    for (int fn = 0; fn < 4; ++fn)
                        mma_f16(d[fm][fn], a[fm], bf[fn]);
            }
        }
    }

    // ---- epilogue: transpose all 256 pix x 128 co through smem ----
    __syncthreads();
    float* smT = (float*)smch;    // [128 co][260 pix]
#pragma unroll
    for (int fm = 0; fm < 4; ++fm) {
#pragma unroll
        for (int fn = 0; fn < 4; ++fn) {
            int m = wm * 64 + fm * 16 + gid;
            int n = wn * 32 + fn * 8 + tig * 2;
            smT[n * 260 + m]           = d[fm][fn][0];
            smT[(n + 1) * 260 + m]     = d[fm][fn][1];
            smT[n * 260 + m + 8]       = d[fm][fn][2];
            smT[(n + 1) * 260 + m + 8] = d[fm][fn][3];
        }
    }
    __syncthreads();

#pragma unroll 4
    for (int i = 0; i < 64; ++i) {
        int idx = i * 512 + tid;
        int co = idx >> 8, pix = idx & 255;
        int pp = p0 + pix;
        if (pp < MPLANE) {
            int r = pp / WPAD;
            int w = pp - r * WPAD;
            if (w >= 1 && w <= 64) {
                float sc = g_scale[b * 512 + co0 + co];
                out[((size_t)(b * 512 + co0 + co)) * HW2 + r * 64 + (w - 1)] =
                    smT[co * 260 + pix] * sc;
            }
        }
    }
}

// ---------------- launch ----------------
extern "C" void kernel_launch(void* const* d_in, const int* in_sizes, int n_in,
                              void* d_out, int out_size) {
    const float* x      = (const float*)d_in[0];
    const float* style  = (const float*)d_in[1];
    const float* weight = (const float*)d_in[2];
    const float* modw   = (const float*)d_in[3];
    const float* modb   = (const float*)d_in[4];
    float* out = (float*)d_out;
    float* out_s5 = out + (size_t)B_ * COUT * HW2;

    static int smem_set = 0;
    if (!smem_set) {
        cudaFuncSetAttribute(conv_kernel, cudaFuncAttributeMaxDynamicSharedMemorySize,
                             SMEM_TOTAL);
        smem_set = 1;
    }

    prep1_kernel<<<544, 512>>>(style, modw, modb, weight, out_s5);
    prep2_kernel<<<2176, 256>>>(x);

    dim3 grid(COUT / BN, 17, B_);   // 4 x 17 x 8 = 544 CTAs
    conv_kernel<<<grid, 512, SMEM_TOTAL>>>(out);
}

// round 9
// speedup vs baseline: 1.0475x; 1.0475x over previous
#include <cuda_runtime.h>
#include <cuda_fp16.h>
#include <cstdint>

// ModulatedConv2d B=8, Cin=Cout=512, K=3, H=W=64
// fp16 mma.sync m16n8k16 implicit GEMM; kw-tap-resident stages, 2 CTAs/SM.

#define B_      8
#define CIN     512
#define COUT    512
#define HW2     4096
#define WPAD    66
#define MPLANE  4224        // 64 rows * 66
#define LIN_SCALE   0.044194173824159216f
#define CONV_SCALE  0.014731391274719739f
#define EPS_        1e-8f

// ---------------- device scratch ----------------
__device__ float  g_s[B_ * CIN];
__device__ float  g_scale[B_ * COUT];
__device__ float  g_wsq[COUT * CIN];
__device__ __half g_xt[(size_t)B_ * MPLANE * CIN];
__device__ __half g_wt[9ull * COUT * CIN];

// ---------------- helpers ----------------
__device__ __forceinline__ uint32_t smem_u32(const void* p) {
    uint32_t a;
    asm("{ .reg .u64 t; cvta.to.shared.u64 t, %1; cvt.u32.u64 %0, t; }" : "=r"(a) : "l"(p));
    return a;
}
__device__ __forceinline__ void cp16(uint32_t dst, const void* src, int srcsize) {
    asm volatile("cp.async.ca.shared.global [%0], [%1], 16, %2;"
                 :: "r"(dst), "l"(src), "r"(srcsize) : "memory");
}
#define CP_COMMIT() asm volatile("cp.async.commit_group;" ::: "memory")
#define CP_WAIT(n)  asm volatile("cp.async.wait_group %0;" :: "n"(n) : "memory")

__device__ __forceinline__ void ldsm4(uint32_t* r, uint32_t addr) {
    asm volatile("ldmatrix.sync.aligned.m8n8.x4.shared.b16 {%0,%1,%2,%3}, [%4];"
        : "=r"(r[0]), "=r"(r[1]), "=r"(r[2]), "=r"(r[3]) : "r"(addr));
}
__device__ __forceinline__ void mma_f16(float* d, const uint32_t* a, const uint32_t* b) {
    asm volatile(
        "mma.sync.aligned.m16n8k16.row.col.f32.f16.f16.f32 "
        "{%0,%1,%2,%3}, {%4,%5,%6,%7}, {%8,%9}, {%0,%1,%2,%3};"
        : "+f"(d[0]), "+f"(d[1]), "+f"(d[2]), "+f"(d[3])
        : "r"(a[0]), "r"(a[1]), "r"(a[2]), "r"(a[3]), "r"(b[0]), "r"(b[1]));
}

// ---------------- prep1: style (blocks 0..31) + wtrans (blocks 32..543), 512 thr ----
__global__ void prep1_kernel(const float* __restrict__ style,
                             const float* __restrict__ modw,
                             const float* __restrict__ modb,
                             const float* __restrict__ weight,
                             float* __restrict__ out_s5) {
    int blk = blockIdx.x, t = threadIdx.x;
    if (blk < 32) {
        __shared__ float st[512];
        int b = blk >> 2;
        st[t] = style[b * 512 + t];
        __syncthreads();
        int ci = (blk & 3) * 128 + (t >> 2);
        int part = t & 3;
        const float4* mrow = (const float4*)(modw + (size_t)ci * 512) + part * 32;
        const float4* s4 = (const float4*)st + part * 32;
        float a0 = 0.f, a1 = 0.f, a2 = 0.f, a3 = 0.f;
#pragma unroll
        for (int j = 0; j < 32; ++j) {
            float4 m = mrow[j], s = s4[j];
            a0 = fmaf(s.x, m.x, a0);
            a1 = fmaf(s.y, m.y, a1);
            a2 = fmaf(s.z, m.z, a2);
            a3 = fmaf(s.w, m.w, a3);
        }
        float acc = (a0 + a1) + (a2 + a3);
        acc += __shfl_xor_sync(0xffffffffu, acc, 1);
        acc += __shfl_xor_sync(0xffffffffu, acc, 2);
        if (part == 0) {
            float s = acc * LIN_SCALE + modb[ci];
            g_s[b * 512 + ci] = s;
            out_s5[b * 512 + ci] = s;
        }
    } else {
        // wtrans: block = co. Stage the 4608-float weight row through smem (coalesced).
        __shared__ float wrow[4608];
        int co = blk - 32;
        const float* wsrc = weight + (size_t)co * 4608;
#pragma unroll
        for (int i = 0; i < 9; ++i) wrow[t + i * 512] = wsrc[t + i * 512];
        __syncthreads();
        int ci = t;
        float w[9], q = 0.f;
#pragma unroll
        for (int k = 0; k < 9; ++k) { w[k] = wrow[ci * 9 + k]; q = fmaf(w[k], w[k], q); }
        g_wsq[co * 512 + ci] = q;
#pragma unroll
        for (int k = 0; k < 9; ++k)
            g_wt[((size_t)k * COUT + co) * 512 + ci] = __float2half_rn(w[k]);
    }
}

// ---------------- prep2: demod (blocks 0..127) + modxt (blocks 128..2175), 256 thr ----
__global__ void prep2_kernel(const float* __restrict__ x) {
    int blk = blockIdx.x, t = threadIdx.x;
    if (blk < 128) {
        __shared__ float s2[512];
        int b = blk >> 4;
        float sv = g_s[b * 512 + t];
        s2[t] = sv * sv;
        sv = g_s[b * 512 + t + 256];
        s2[t + 256] = sv * sv;
        __syncthreads();
        int co = (blk & 15) * 32 + (t >> 3);
        int part = t & 7;
        const float4* wq = (const float4*)(g_wsq + (size_t)co * 512) + part * 16;
        const float4* s4 = (const float4*)s2 + part * 16;
        float a0 = 0.f, a1 = 0.f, a2 = 0.f, a3 = 0.f;
#pragma unroll
        for (int j = 0; j < 16; ++j) {
            float4 m = wq[j], s = s4[j];
            a0 = fmaf(s.x, m.x, a0);
            a1 = fmaf(s.y, m.y, a1);
            a2 = fmaf(s.z, m.z, a2);
            a3 = fmaf(s.w, m.w, a3);
        }
        float acc = (a0 + a1) + (a2 + a3);
        acc += __shfl_xor_sync(0xffffffffu, acc, 1);
        acc += __shfl_xor_sync(0xffffffffu, acc, 2);
        acc += __shfl_xor_sync(0xffffffffu, acc, 4);
        if (part == 0)
            g_scale[b * 512 + co] = CONV_SCALE * rsqrtf(CONV_SCALE * CONV_SCALE * acc + EPS_);
    } else {
        __shared__ float tt[64][65];
        int idx = blk - 128;               // 0..2047
        int cg  = idx & 3;
        int row = (idx >> 2) & 63;
        int b   = idx >> 8;
        __half* obase = g_xt + ((size_t)b * MPLANE + (size_t)row * WPAD) * CIN;
        if (t < 256) {
            int which = t >> 7, col = (t & 127) + cg * 128;
            obase[(size_t)which * 65 * CIN + col] = __float2half_rn(0.f);
        }
        for (int cc = 0; cc < 2; ++cc) {
            int cic = cg * 2 + cc;
            __syncthreads();
            for (int i = t; i < 4096; i += 256) {
                int ci = i >> 6, w = i & 63;
                float s = g_s[b * 512 + cic * 64 + ci];
                tt[ci][w] = x[((size_t)(b * 512 + cic * 64 + ci)) * HW2 + row * 64 + w] * s;
            }
            __syncthreads();
            for (int i = t; i < 4096; i += 256) {
                int w = i >> 6, ci = i & 63;
                obase[(size_t)(1 + w) * CIN + cic * 64 + ci] = __float2half_rn(tt[ci][w]);
            }
        }
    }
}

// ---------------- conv: tap-resident fp16 GEMM ----------------
// Stage = (kc: 32 ci, kh). A slab (130 rows covers all 3 kw) + 3 kw weight tiles.
// 48 stages, double-buffered, 2 CTAs/SM.
#define BM 128
#define BN 128
#define KSTR 40                      // smem row stride (halves); conflict-free for ldmatrix
#define AROWS 132
#define ASZH (AROWS * KSTR)          // 5280 halves
#define BSZH (3 * 128 * KSTR)        // 15360 halves
#define ABYTES (ASZH * 2)            // 10560
#define STAGEB ((ASZH + BSZH) * 2)   // 41280
#define NST 48
#define SMEM_TOTAL (2 * STAGEB)      // 82560

__global__ __launch_bounds__(256, 2)
void conv_kernel(float* __restrict__ out) {
    extern __shared__ char smch[];

    const int tid = threadIdx.x;
    const int warp = tid >> 5, lane = tid & 31;
    const int wm = warp & 1;
    const int wn = warp >> 1;
    const int gid = lane >> 2;
    const int tig = lane & 3;

    const int co0 = blockIdx.x * BN;
    const int p0 = blockIdx.y * BM;
    const int b = blockIdx.z;

    const __half* Abase = g_xt + (size_t)b * MPLANE * CIN;
    const uint32_t sb = smem_u32(smch);

    const uint32_t a_loff = (((lane & 7) + ((lane >> 3) & 1) * 8) * KSTR + (lane >> 4) * 8) * 2u;
    const uint32_t b_loff = (((lane & 7) + ((lane >> 4) & 1) * 8) * KSTR + ((lane >> 3) & 1) * 8) * 2u;

    float d[4][4][4];
#pragma unroll
    for (int i = 0; i < 4; ++i)
#pragma unroll
        for (int j = 0; j < 4; ++j)
#pragma unroll
            for (int k = 0; k < 4; ++k) d[i][j][k] = 0.f;

    auto load_stage = [&](int s, int buf) {
        const int kc = s / 3, kh = s % 3;
        const uint32_t a0 = sb + (uint32_t)buf * STAGEB;
        const uint32_t b0 = a0 + ABYTES;
        const int prbase = p0 + (kh - 1) * WPAD - 1;
        // A: 130 rows (halo +-1 in kw dir), 528 cp16
#pragma unroll
        for (int i = 0; i < 3; ++i) {
            int idx = tid + i * 256;
            if (idx < 528) {
                int row = idx >> 2, q = idx & 3;
                int pr = prbase + row;
                const __half* src = Abase + (size_t)pr * CIN + kc * 32 + q * 8;
                int sz = ((unsigned)pr < (unsigned)MPLANE) ? 16 : 0;
                cp16(a0 + (uint32_t)(row * KSTR + q * 8) * 2u, src, sz);
            }
        }
        // B: 3 kw taps x 128 co x 4 q = 1536 cp16
#pragma unroll
        for (int i = 0; i < 6; ++i) {
            int idx = tid + i * 256;
            int kw = idx >> 9;
            int r = idx & 511;
            int co = r >> 2, q = r & 3;
            const __half* src = g_wt + ((size_t)(kh * 3 + kw) * COUT + co0 + co) * CIN
                                + kc * 32 + q * 8;
            cp16(b0 + (uint32_t)((kw * 128 + co) * KSTR + q * 8) * 2u, src, 16);
        }
        CP_COMMIT();
    };

    load_stage(0, 0);

    for (int s = 0; s < NST; ++s) {
        CP_WAIT(0);
        __syncthreads();
        if (s + 1 < NST) load_stage(s + 1, (s + 1) & 1);

        const uint32_t a0 = sb + (uint32_t)(s & 1) * STAGEB;
        const uint32_t b0 = a0 + ABYTES;
#pragma unroll
        for (int kw = 0; kw < 3; ++kw) {
#pragma unroll
            for (int ks = 0; ks < 2; ++ks) {
                const int kb = ks * 16;
                uint32_t a[4][4];
#pragma unroll
                for (int fm = 0; fm < 4; ++fm)
                    ldsm4(a[fm], a0 + (uint32_t)((wm * 64 + fm * 16 + kw) * KSTR + kb) * 2u + a_loff);
                uint32_t bf[4][2];
#pragma unroll
                for (int j = 0; j < 2; ++j) {
                    uint32_t r[4];
                    ldsm4(r, b0 + (uint32_t)((kw * 128 + wn * 32 + j * 16) * KSTR + kb) * 2u + b_loff);
                    bf[2 * j][0] = r[0]; bf[2 * j][1] = r[1];
                    bf[2 * j + 1][0] = r[2]; bf[2 * j + 1][1] = r[3];
                }
#pragma unroll
                for (int fm = 0; fm < 4; ++fm)
#pragma unroll
                    for (int fn = 0; fn < 4; ++fn)
                        mma_f16(d[fm][fn], a[fm], bf[fn]);
            }
        }
    }

    // ---- epilogue: transpose through smem, coalesced scaled stores ----
    __syncthreads();
    float* smT = (float*)smch;    // [128 co][132 pix]
#pragma unroll
    for (int fm = 0; fm < 4; ++fm) {
#pragma unroll
        for (int fn = 0; fn < 4; ++fn) {
            int m = wm * 64 + fm * 16 + gid;
            int n = wn * 32 + fn * 8 + tig * 2;
            smT[n * 132 + m]           = d[fm][fn][0];
            smT[(n + 1) * 132 + m]     = d[fm][fn][1];
            smT[n * 132 + m + 8]       = d[fm][fn][2];
            smT[(n + 1) * 132 + m + 8] = d[fm][fn][3];
        }
    }
    __syncthreads();

#pragma unroll 4
    for (int i = 0; i < 64; ++i) {
        int idx = i * 256 + tid;
        int co = idx >> 7, pix = idx & 127;
        int pp = p0 + pix;
        int r = pp / WPAD;
        int w = pp - r * WPAD;
        if (w >= 1 && w <= 64) {
            float sc = g_scale[b * 512 + co0 + co];
            out[((size_t)(b * 512 + co0 + co)) * HW2 + r * 64 + (w - 1)] =
                smT[co * 132 + pix] * sc;
        }
    }
}

// ---------------- marker: aligns ncu capture slot onto conv_kernel ----------------
__global__ void marker_kernel() {}

// ---------------- launch ----------------
extern "C" void kernel_launch(void* const* d_in, const int* in_sizes, int n_in,
                              void* d_out, int out_size) {
    const float* x      = (const float*)d_in[0];
    const float* style  = (const float*)d_in[1];
    const float* weight = (const float*)d_in[2];
    const float* modw   = (const float*)d_in[3];
    const float* modb   = (const float*)d_in[4];
    float* out = (float*)d_out;
    float* out_s5 = out + (size_t)B_ * COUT * HW2;

    static int smem_set = 0;
    if (!smem_set) {
        cudaFuncSetAttribute(conv_kernel, cudaFuncAttributeMaxDynamicSharedMemorySize,
                             SMEM_TOTAL);
        smem_set = 1;
    }

    prep1_kernel<<<544, 512>>>(style, modw, modb, weight, out_s5);
    prep2_kernel<<<2176, 256>>>(x);

    dim3 grid(COUT / BN, 33, B_);   // 4 x 33 x 8 = 1056 CTAs
    conv_kernel<<<grid, 256, SMEM_TOTAL>>>(out);

    marker_kernel<<<1, 32>>>();     // pads the launch group to 4 so the ncu
                                    // capture slot (launch #7) lands on conv_kernel
}